// round 1
// baseline (speedup 1.0000x reference)
#include <cuda_runtime.h>

// ---------------- problem constants ----------------
#define BSZ  4
#define SEQ  2048
#define CH   768
#define NH   12
#define HD   64
#define BHN  (BSZ*NH)          // 48

// ---------------- scratch (no cudaMalloc allowed) ----------------
__device__ float g_q[(size_t)BHN*SEQ*HD];   // [bh][n][d]
__device__ float g_k[(size_t)BHN*SEQ*HD];
__device__ float g_v[(size_t)BHN*SEQ*HD];
__device__ float g_o[(size_t)BSZ*SEQ*CH];   // [b*n][c] attention output

// =====================================================================
// GEMM 1: qkv = x @ w_qkv   (M=8192, K=768, N=2304), scatter epilogue
// 128x128 block tile, BK=8, 256 threads, 8x8 per-thread microkernel.
// =====================================================================
__global__ __launch_bounds__(256) void qkv_gemm(const float* __restrict__ A,
                                                const float* __restrict__ Bw)
{
    const int N = 3 * CH;     // 2304
    const int K = CH;         // 768
    __shared__ float As[8 * 128];   // [k][m] transposed
    __shared__ float Bs[8 * 128];   // [k][n]

    const int n0 = blockIdx.x * 128;
    const int m0 = blockIdx.y * 128;
    const int tid = threadIdx.x;
    const int tx = tid & 15, ty = tid >> 4;

    const int arow = tid >> 1;            // 0..127
    const int ac   = (tid & 1) * 4;       // 0 or 4
    const int brow = tid >> 5;            // 0..7
    const int bc   = (tid & 31) * 4;      // 0..124

    const float* Ap = A  + (size_t)(m0 + arow) * K + ac;
    const float* Bp = Bw + (size_t)brow * N + n0 + bc;

    float acc[8][8];
#pragma unroll
    for (int i = 0; i < 8; ++i)
#pragma unroll
        for (int j = 0; j < 8; ++j) acc[i][j] = 0.f;

    float4 pa = *(const float4*)Ap;
    float4 pb = *(const float4*)Bp;
    const int NT = K / 8;   // 96

    for (int t = 0;;) {
        As[(ac + 0) * 128 + arow] = pa.x;
        As[(ac + 1) * 128 + arow] = pa.y;
        As[(ac + 2) * 128 + arow] = pa.z;
        As[(ac + 3) * 128 + arow] = pa.w;
        *(float4*)&Bs[brow * 128 + bc] = pb;
        __syncthreads();

        if (t + 1 < NT) {
            pa = *(const float4*)(Ap + (t + 1) * 8);
            pb = *(const float4*)(Bp + (size_t)(t + 1) * 8 * N);
        }

#pragma unroll
        for (int kk = 0; kk < 8; ++kk) {
            float a[8], b[8];
            *(float4*)&a[0] = *(const float4*)&As[kk * 128 + ty * 4];
            *(float4*)&a[4] = *(const float4*)&As[kk * 128 + 64 + ty * 4];
            *(float4*)&b[0] = *(const float4*)&Bs[kk * 128 + tx * 4];
            *(float4*)&b[4] = *(const float4*)&Bs[kk * 128 + 64 + tx * 4];
#pragma unroll
            for (int i = 0; i < 8; ++i)
#pragma unroll
                for (int j = 0; j < 8; ++j)
                    acc[i][j] += a[i] * b[j];
        }
        if (++t == NT) break;
        __syncthreads();
    }

    // scatter into q/k/v [bh][n][d]
#pragma unroll
    for (int i = 0; i < 8; ++i) {
        const int r  = m0 + ((i < 4) ? (ty * 4 + i) : (60 + ty * 4 + i));
        const int bb = r >> 11;          // batch
        const int n  = r & (SEQ - 1);
#pragma unroll
        for (int jh = 0; jh < 2; ++jh) {
            const int col = n0 + jh * 64 + tx * 4;
            const int t3  = col / CH;
            const int rem = col - t3 * CH;
            const int h   = rem >> 6;
            const int d   = rem & 63;
            float* dst = (t3 == 0) ? g_q : ((t3 == 1) ? g_k : g_v);
            float4 v = make_float4(acc[i][jh * 4 + 0], acc[i][jh * 4 + 1],
                                   acc[i][jh * 4 + 2], acc[i][jh * 4 + 3]);
            *(float4*)&dst[(((size_t)bb * NH + h) * SEQ + n) * HD + d] = v;
        }
    }
}

// =====================================================================
// Flash attention (causal), fp32. One block = 128 query rows of one
// (b,h). Streams 128-wide K/V tiles with online softmax.
// smem: Qs[64][128] (d-major, pre-scaled), Ks[64][128], Vs[128][64],
//       Ps[128][128] (col-major, XOR-swizzled) = 160 KB dynamic.
// =====================================================================
__device__ __forceinline__ int pswz(int c) {
    return ((c >> 2) ^ ((c & 3) << 3)) & 31;
}

__global__ __launch_bounds__(256, 1) void attn_kernel()
{
    extern __shared__ float sm[];
    float* Qs = sm;                 // 64*128
    float* Ks = sm + 8192;          // 64*128
    float* Vs = sm + 16384;         // 128*64
    float* Ps = sm + 24576;         // 128*128

    const int bh = blockIdx.y;
    const int it = (gridDim.x - 1) - blockIdx.x;   // longest blocks first
    const int r0 = it * 128;

    const float* Qg = g_q + (size_t)bh * (SEQ * HD);
    const float* Kg = g_k + (size_t)bh * (SEQ * HD);
    const float* Vg = g_v + (size_t)bh * (SEQ * HD);

    const int tid = threadIdx.x;
    const int tx = tid & 15, ty = tid >> 4;

    // ---- load Q tile transposed [d][row], folding in softmax scale ----
    {
        const int row = tid >> 1, half = tid & 1;
        const float* qp = Qg + (size_t)(r0 + row) * HD + half * 32;
#pragma unroll
        for (int j = 0; j < 8; ++j) {
            float4 v = *(const float4*)(qp + j * 4);
            const int d0 = half * 32 + j * 4;
            Qs[(d0 + 0) * 128 + row] = v.x * 0.125f;
            Qs[(d0 + 1) * 128 + row] = v.y * 0.125f;
            Qs[(d0 + 2) * 128 + row] = v.z * 0.125f;
            Qs[(d0 + 3) * 128 + row] = v.w * 0.125f;
        }
    }

    float o[8][4];
    float m[8], l[8];
#pragma unroll
    for (int i = 0; i < 8; ++i) {
        m[i] = -1e30f; l[i] = 0.f;
        o[i][0] = o[i][1] = o[i][2] = o[i][3] = 0.f;
    }

    for (int jt = 0; jt <= it; ++jt) {
        const int c0 = jt * 128;
        __syncthreads();   // previous PV / S done with Ks,Vs,Ps (and Q visible)

        // ---- load K transposed [d][col] and V straight [col][d] ----
        {
            const int col = tid >> 1, half = tid & 1;
            const float* kp = Kg + (size_t)(c0 + col) * HD + half * 32;
#pragma unroll
            for (int j = 0; j < 8; ++j) {
                float4 v = *(const float4*)(kp + j * 4);
                const int d0 = half * 32 + j * 4;
                Ks[(d0 + 0) * 128 + col] = v.x;
                Ks[(d0 + 1) * 128 + col] = v.y;
                Ks[(d0 + 2) * 128 + col] = v.z;
                Ks[(d0 + 3) * 128 + col] = v.w;
            }
            const float4* vsrc = (const float4*)(Vg + (size_t)c0 * HD);
            float4* vdst = (float4*)Vs;
#pragma unroll
            for (int j = 0; j < 8; ++j)
                vdst[j * 256 + tid] = vsrc[j * 256 + tid];
        }
        __syncthreads();

        // ---- S = (Q*scale) @ K^T : 8x8 scores per thread ----
        float s[8][8];
#pragma unroll
        for (int i = 0; i < 8; ++i)
#pragma unroll
            for (int j = 0; j < 8; ++j) s[i][j] = 0.f;

#pragma unroll 4
        for (int dd = 0; dd < 64; ++dd) {
            float a[8], b[8];
            *(float4*)&a[0] = *(const float4*)&Qs[dd * 128 + ty * 4];
            *(float4*)&a[4] = *(const float4*)&Qs[dd * 128 + 64 + ty * 4];
            *(float4*)&b[0] = *(const float4*)&Ks[dd * 128 + tx * 4];
            *(float4*)&b[4] = *(const float4*)&Ks[dd * 128 + 64 + tx * 4];
#pragma unroll
            for (int i = 0; i < 8; ++i)
#pragma unroll
                for (int j = 0; j < 8; ++j)
                    s[i][j] += a[i] * b[j];
        }

        // ---- causal mask (diagonal tile only) + online softmax ----
        const bool diag = (jt == it);
#pragma unroll
        for (int i = 0; i < 8; ++i) {
            const int rg = r0 + ((i < 4) ? (ty * 4 + i) : (60 + ty * 4 + i));
            if (diag) {
#pragma unroll
                for (int j = 0; j < 8; ++j) {
                    const int cg = c0 + ((j < 4) ? (tx * 4 + j) : (60 + tx * 4 + j));
                    if (cg > rg) s[i][j] = -1e30f;
                }
            }
            float mx = s[i][0];
#pragma unroll
            for (int j = 1; j < 8; ++j) mx = fmaxf(mx, s[i][j]);
            mx = fmaxf(mx, __shfl_xor_sync(0xffffffffu, mx, 1));
            mx = fmaxf(mx, __shfl_xor_sync(0xffffffffu, mx, 2));
            mx = fmaxf(mx, __shfl_xor_sync(0xffffffffu, mx, 4));
            mx = fmaxf(mx, __shfl_xor_sync(0xffffffffu, mx, 8));

            const float mnew = fmaxf(m[i], mx);
            const float corr = __expf(m[i] - mnew);
            float sum = 0.f;
#pragma unroll
            for (int j = 0; j < 8; ++j) {
                s[i][j] = __expf(s[i][j] - mnew);
                sum += s[i][j];
            }
            sum += __shfl_xor_sync(0xffffffffu, sum, 1);
            sum += __shfl_xor_sync(0xffffffffu, sum, 2);
            sum += __shfl_xor_sync(0xffffffffu, sum, 4);
            sum += __shfl_xor_sync(0xffffffffu, sum, 8);

            l[i] = l[i] * corr + sum;
            m[i] = mnew;
            o[i][0] *= corr; o[i][1] *= corr; o[i][2] *= corr; o[i][3] *= corr;
        }

        // ---- write P to smem, col-major + XOR swizzle (conflict-free) ----
#pragma unroll
        for (int j = 0; j < 8; ++j) {
            const int c = (j < 4) ? (tx * 4 + j) : (60 + tx * 4 + j);
            const int sw = pswz(c);
            *(float4*)&Ps[c * 128 + ((ty ^ sw) << 2)] =
                make_float4(s[0][j], s[1][j], s[2][j], s[3][j]);
            *(float4*)&Ps[c * 128 + (((ty + 16) ^ sw) << 2)] =
                make_float4(s[4][j], s[5][j], s[6][j], s[7][j]);
        }
        __syncthreads();

        // ---- O += P @ V : 8 rows x 4 d per thread ----
#pragma unroll 2
        for (int cc = 0; cc < 128; ++cc) {
            const int sw = pswz(cc);
            float a[8], bv[4];
            *(float4*)&a[0] = *(const float4*)&Ps[cc * 128 + ((ty ^ sw) << 2)];
            *(float4*)&a[4] = *(const float4*)&Ps[cc * 128 + (((ty + 16) ^ sw) << 2)];
            *(float4*)&bv[0] = *(const float4*)&Vs[cc * 64 + tx * 4];
#pragma unroll
            for (int i = 0; i < 8; ++i)
#pragma unroll
                for (int j = 0; j < 4; ++j)
                    o[i][j] += a[i] * bv[j];
        }
    }

    // ---- normalize + write to g_o [b*n][c] ----
    const int b = bh / NH, h = bh % NH;
#pragma unroll
    for (int i = 0; i < 8; ++i) {
        const int r = r0 + ((i < 4) ? (ty * 4 + i) : (60 + ty * 4 + i));
        const float inv = 1.0f / l[i];
        float4 v = make_float4(o[i][0] * inv, o[i][1] * inv,
                               o[i][2] * inv, o[i][3] * inv);
        *(float4*)&g_o[((size_t)b * SEQ + r) * CH + h * 64 + tx * 4] = v;
    }
}

// =====================================================================
// GEMM 2: out = g_o @ w_proj + b_proj   (M=8192, K=768, N=768)
// =====================================================================
__global__ __launch_bounds__(256) void proj_gemm(const float* __restrict__ Bw,
                                                 const float* __restrict__ bias,
                                                 float* __restrict__ out)
{
    const int N = CH, K = CH;
    __shared__ float As[8 * 128];
    __shared__ float Bs[8 * 128];

    const int n0 = blockIdx.x * 128;
    const int m0 = blockIdx.y * 128;
    const int tid = threadIdx.x;
    const int tx = tid & 15, ty = tid >> 4;

    const int arow = tid >> 1;
    const int ac   = (tid & 1) * 4;
    const int brow = tid >> 5;
    const int bc   = (tid & 31) * 4;

    const float* Ap = g_o + (size_t)(m0 + arow) * K + ac;
    const float* Bp = Bw  + (size_t)brow * N + n0 + bc;

    float acc[8][8];
#pragma unroll
    for (int i = 0; i < 8; ++i)
#pragma unroll
        for (int j = 0; j < 8; ++j) acc[i][j] = 0.f;

    float4 pa = *(const float4*)Ap;
    float4 pb = *(const float4*)Bp;
    const int NT = K / 8;

    for (int t = 0;;) {
        As[(ac + 0) * 128 + arow] = pa.x;
        As[(ac + 1) * 128 + arow] = pa.y;
        As[(ac + 2) * 128 + arow] = pa.z;
        As[(ac + 3) * 128 + arow] = pa.w;
        *(float4*)&Bs[brow * 128 + bc] = pb;
        __syncthreads();

        if (t + 1 < NT) {
            pa = *(const float4*)(Ap + (t + 1) * 8);
            pb = *(const float4*)(Bp + (size_t)(t + 1) * 8 * N);
        }

#pragma unroll
        for (int kk = 0; kk < 8; ++kk) {
            float a[8], b[8];
            *(float4*)&a[0] = *(const float4*)&As[kk * 128 + ty * 4];
            *(float4*)&a[4] = *(const float4*)&As[kk * 128 + 64 + ty * 4];
            *(float4*)&b[0] = *(const float4*)&Bs[kk * 128 + tx * 4];
            *(float4*)&b[4] = *(const float4*)&Bs[kk * 128 + 64 + tx * 4];
#pragma unroll
            for (int i = 0; i < 8; ++i)
#pragma unroll
                for (int j = 0; j < 8; ++j)
                    acc[i][j] += a[i] * b[j];
        }
        if (++t == NT) break;
        __syncthreads();
    }

#pragma unroll
    for (int i = 0; i < 8; ++i) {
        const int r = m0 + ((i < 4) ? (ty * 4 + i) : (60 + ty * 4 + i));
#pragma unroll
        for (int jh = 0; jh < 2; ++jh) {
            const int col = n0 + jh * 64 + tx * 4;
            float4 bv = *(const float4*)&bias[col];
            float4 v = make_float4(acc[i][jh * 4 + 0] + bv.x,
                                   acc[i][jh * 4 + 1] + bv.y,
                                   acc[i][jh * 4 + 2] + bv.z,
                                   acc[i][jh * 4 + 3] + bv.w);
            *(float4*)&out[(size_t)r * CH + col] = v;
        }
    }
}

// =====================================================================
// launch
// =====================================================================
extern "C" void kernel_launch(void* const* d_in, const int* in_sizes, int n_in,
                              void* d_out, int out_size)
{
    (void)in_sizes; (void)n_in; (void)out_size;
    const float* x      = (const float*)d_in[0];
    const float* w_qkv  = (const float*)d_in[1];
    const float* w_proj = (const float*)d_in[2];
    const float* b_proj = (const float*)d_in[3];
    float* out = (float*)d_out;

    cudaFuncSetAttribute((const void*)attn_kernel,
                         cudaFuncAttributeMaxDynamicSharedMemorySize, 163840);

    qkv_gemm<<<dim3(18, 64), 256>>>(x, w_qkv);
    attn_kernel<<<dim3(16, 48), 256, 163840>>>();
    proj_gemm<<<dim3(6, 64), 256>>>(w_proj, b_proj, out);
}

// round 3
// speedup vs baseline: 1.3025x; 1.3025x over previous
#include <cuda_runtime.h>
#include <cstdint>

// ---------------- problem constants ----------------
#define BSZ  4
#define SEQ  2048
#define CH   768
#define NH   12
#define HD   64
#define BHN  (BSZ*NH)          // 48

// ---------------- scratch (no cudaMalloc allowed) ----------------
__device__ float g_q[(size_t)BHN*SEQ*HD];   // [bh][n][d]
__device__ float g_k[(size_t)BHN*SEQ*HD];
__device__ float g_v[(size_t)BHN*SEQ*HD];
__device__ float g_o[(size_t)BSZ*SEQ*CH];   // [b*n][c] attention output

// ---------------- helpers ----------------
__device__ __forceinline__ uint32_t f2tf32(float x) {   // round-to-nearest tf32
    uint32_t u; asm("cvt.rna.tf32.f32 %0, %1;" : "=r"(u) : "f"(x)); return u;
}

// D += A(16x8,row) * B(8x8,col)  tf32
__device__ __forceinline__ void mma8(float* c, const uint32_t* a, const uint32_t* b) {
    asm("mma.sync.aligned.m16n8k8.row.col.f32.tf32.tf32.f32 "
        "{%0,%1,%2,%3}, {%4,%5,%6,%7}, {%8,%9}, {%0,%1,%2,%3};"
        : "+f"(c[0]), "+f"(c[1]), "+f"(c[2]), "+f"(c[3])
        : "r"(a[0]), "r"(a[1]), "r"(a[2]), "r"(a[3]), "r"(b[0]), "r"(b[1]));
}

// =====================================================================
// tf32 mma GEMM core: C[128x128] = A[128xK] * B[Kx128-slice]
// A row-major [M][768], B row-major [768][nstride] (k-major).
// smem: As/Bs [2 buf][16 k][128], XOR-8 swizzled: col = n ^ (8*(k&3)).
// 8 warps, warp tile 32m x 64n, acc in D-fragment layout.
// =====================================================================
__device__ __forceinline__ void gemm_core(const float* __restrict__ A,
                                          const float* __restrict__ B,
                                          int m0, int n0, int nstride,
                                          uint32_t* __restrict__ As,
                                          uint32_t* __restrict__ Bs,
                                          float acc[2][8][4])
{
    const int tid  = threadIdx.x;
    const int lane = tid & 31;
    const int wid  = tid >> 5;
    const int g    = lane >> 2;      // 0..7
    const int t    = lane & 3;       // 0..3
    const int wm   = (wid >> 1) * 32;
    const int wn   = (wid & 1) * 64;

    const int am = tid >> 2;         // 0..63 (+64 on second)
    const int ac = tid & 3;          // k-chunk
    const int bk = tid >> 5;         // 0..7  (+8 on second)
    const int bu = tid & 31;

#pragma unroll
    for (int mt = 0; mt < 2; ++mt)
#pragma unroll
        for (int nt = 0; nt < 8; ++nt)
#pragma unroll
            for (int j = 0; j < 4; ++j) acc[mt][nt][j] = 0.f;

    const int NT = CH / 16;          // 48
    float4 ra[2], rb[2];

    // prologue: load tile 0
#pragma unroll
    for (int i = 0; i < 2; ++i) {
        ra[i] = *(const float4*)(A + (size_t)(m0 + am + i * 64) * CH + ac * 4);
        rb[i] = *(const float4*)(B + (size_t)(bk + i * 8) * nstride + n0 + bu * 4);
    }

    for (int kt = 0; kt < NT; ++kt) {
        const int buf = kt & 1;
        uint32_t* Ab = As + buf * 2048;
        uint32_t* Bb = Bs + buf * 2048;

        // store current regs -> smem buf
        {
#pragma unroll
            for (int i = 0; i < 2; ++i) {
                const float v[4] = {ra[i].x, ra[i].y, ra[i].z, ra[i].w};
                const int m = am + i * 64;
#pragma unroll
                for (int s = 0; s < 4; ++s) {
                    const int comp = (s + ac) & 3;
                    const int k = ac * 4 + comp;
                    Ab[k * 128 + (m ^ (comp << 3))] = f2tf32(v[comp]);
                }
                const int kk = bk + i * 8;
                uint4 w = make_uint4(f2tf32(rb[i].x), f2tf32(rb[i].y),
                                     f2tf32(rb[i].z), f2tf32(rb[i].w));
                *(uint4*)&Bb[kk * 128 + ((bu * 4) ^ ((kk & 3) << 3))] = w;
            }
        }
        __syncthreads();

        // prefetch next tile
        if (kt + 1 < NT) {
            const int k0 = (kt + 1) * 16;
#pragma unroll
            for (int i = 0; i < 2; ++i) {
                ra[i] = *(const float4*)(A + (size_t)(m0 + am + i * 64) * CH + k0 + ac * 4);
                rb[i] = *(const float4*)(B + (size_t)(k0 + bk + i * 8) * nstride + n0 + bu * 4);
            }
        }

        // compute 2 k-slices of 8
#pragma unroll
        for (int ks = 0; ks < 2; ++ks) {
            const int krow = ks * 8 + t;
            const int sw = t << 3;
            uint32_t afr[2][4];
#pragma unroll
            for (int mt = 0; mt < 2; ++mt) {
                const int mb = wm + mt * 16 + g;
                afr[mt][0] = Ab[krow * 128 + (mb ^ sw)];
                afr[mt][1] = Ab[krow * 128 + ((mb + 8) ^ sw)];
                afr[mt][2] = Ab[(krow + 4) * 128 + (mb ^ sw)];
                afr[mt][3] = Ab[(krow + 4) * 128 + ((mb + 8) ^ sw)];
            }
#pragma unroll
            for (int nt = 0; nt < 8; ++nt) {
                const int nb = wn + nt * 8 + g;
                uint32_t bfr[2];
                bfr[0] = Bb[krow * 128 + (nb ^ sw)];
                bfr[1] = Bb[(krow + 4) * 128 + (nb ^ sw)];
                mma8(acc[0][nt], afr[0], bfr);
                mma8(acc[1][nt], afr[1], bfr);
            }
        }
        __syncthreads();
    }
}

// =====================================================================
// GEMM 1: qkv = x @ w_qkv, scatter epilogue into g_q/g_k/g_v
// =====================================================================
__global__ __launch_bounds__(256, 2) void qkv_mma(const float* __restrict__ x,
                                                  const float* __restrict__ w)
{
    __shared__ uint32_t As[2 * 2048];
    __shared__ uint32_t Bs[2 * 2048];
    float acc[2][8][4];

    const int m0 = blockIdx.y * 128;
    const int n0 = blockIdx.x * 128;
    gemm_core(x, w, m0, n0, 3 * CH, As, Bs, acc);

    const int tid = threadIdx.x;
    const int lane = tid & 31, wid = tid >> 5;
    const int g = lane >> 2, t = lane & 3;
    const int wm = (wid >> 1) * 32, wn = (wid & 1) * 64;

    const int t3 = blockIdx.x / 6;               // 0:q 1:k 2:v
    const int nb = (blockIdx.x % 6) * 128;
    float* dst = (t3 == 0) ? g_q : (t3 == 1) ? g_k : g_v;

#pragma unroll
    for (int mt = 0; mt < 2; ++mt) {
        const int r = m0 + wm + mt * 16 + g;
        const int b = r >> 11, n = r & (SEQ - 1);
#pragma unroll
        for (int nt = 0; nt < 8; ++nt) {
            const int cb = nb + wn + nt * 8 + 2 * t;
            const int h = cb >> 6, d = cb & 63;
            float* p = dst + (((size_t)b * NH + h) * SEQ + n) * HD + d;
            *(float2*)p = make_float2(acc[mt][nt][0], acc[mt][nt][1]);
            *(float2*)(p + 8 * HD) = make_float2(acc[mt][nt][2], acc[mt][nt][3]);
        }
    }
}

// =====================================================================
// GEMM 2: out = g_o @ w_proj + bias
// =====================================================================
__global__ __launch_bounds__(256, 2) void proj_mma(const float* __restrict__ w,
                                                   const float* __restrict__ bias,
                                                   float* __restrict__ out)
{
    __shared__ uint32_t As[2 * 2048];
    __shared__ uint32_t Bs[2 * 2048];
    float acc[2][8][4];

    const int m0 = blockIdx.y * 128;
    const int n0 = blockIdx.x * 128;
    gemm_core(g_o, w, m0, n0, CH, As, Bs, acc);

    const int tid = threadIdx.x;
    const int lane = tid & 31, wid = tid >> 5;
    const int g = lane >> 2, t = lane & 3;
    const int wm = (wid >> 1) * 32, wn = (wid & 1) * 64;

#pragma unroll
    for (int mt = 0; mt < 2; ++mt) {
        const int r = m0 + wm + mt * 16 + g;
#pragma unroll
        for (int nt = 0; nt < 8; ++nt) {
            const int col = n0 + wn + nt * 8 + 2 * t;
            const float2 bv = *(const float2*)(bias + col);
            float* p = out + (size_t)r * CH + col;
            *(float2*)p = make_float2(acc[mt][nt][0] + bv.x, acc[mt][nt][1] + bv.y);
            *(float2*)(p + 8 * CH) = make_float2(acc[mt][nt][2] + bv.x,
                                                 acc[mt][nt][3] + bv.y);
        }
    }
}

// =====================================================================
// Flash attention (causal), fp32 — UNCHANGED from passing R1 kernel.
// =====================================================================
__device__ __forceinline__ int pswz(int c) {
    return ((c >> 2) ^ ((c & 3) << 3)) & 31;
}

__global__ __launch_bounds__(256, 1) void attn_kernel()
{
    extern __shared__ float sm[];
    float* Qs = sm;                 // 64*128
    float* Ks = sm + 8192;          // 64*128
    float* Vs = sm + 16384;         // 128*64
    float* Ps = sm + 24576;         // 128*128

    const int bh = blockIdx.y;
    const int it = (gridDim.x - 1) - blockIdx.x;   // longest blocks first
    const int r0 = it * 128;

    const float* Qg = g_q + (size_t)bh * (SEQ * HD);
    const float* Kg = g_k + (size_t)bh * (SEQ * HD);
    const float* Vg = g_v + (size_t)bh * (SEQ * HD);

    const int tid = threadIdx.x;
    const int tx = tid & 15, ty = tid >> 4;

    {
        const int row = tid >> 1, half = tid & 1;
        const float* qp = Qg + (size_t)(r0 + row) * HD + half * 32;
#pragma unroll
        for (int j = 0; j < 8; ++j) {
            float4 v = *(const float4*)(qp + j * 4);
            const int d0 = half * 32 + j * 4;
            Qs[(d0 + 0) * 128 + row] = v.x * 0.125f;
            Qs[(d0 + 1) * 128 + row] = v.y * 0.125f;
            Qs[(d0 + 2) * 128 + row] = v.z * 0.125f;
            Qs[(d0 + 3) * 128 + row] = v.w * 0.125f;
        }
    }

    float o[8][4];
    float m[8], l[8];
#pragma unroll
    for (int i = 0; i < 8; ++i) {
        m[i] = -1e30f; l[i] = 0.f;
        o[i][0] = o[i][1] = o[i][2] = o[i][3] = 0.f;
    }

    for (int jt = 0; jt <= it; ++jt) {
        const int c0 = jt * 128;
        __syncthreads();

        {
            const int col = tid >> 1, half = tid & 1;
            const float* kp = Kg + (size_t)(c0 + col) * HD + half * 32;
#pragma unroll
            for (int j = 0; j < 8; ++j) {
                float4 v = *(const float4*)(kp + j * 4);
                const int d0 = half * 32 + j * 4;
                Ks[(d0 + 0) * 128 + col] = v.x;
                Ks[(d0 + 1) * 128 + col] = v.y;
                Ks[(d0 + 2) * 128 + col] = v.z;
                Ks[(d0 + 3) * 128 + col] = v.w;
            }
            const float4* vsrc = (const float4*)(Vg + (size_t)c0 * HD);
            float4* vdst = (float4*)Vs;
#pragma unroll
            for (int j = 0; j < 8; ++j)
                vdst[j * 256 + tid] = vsrc[j * 256 + tid];
        }
        __syncthreads();

        float s[8][8];
#pragma unroll
        for (int i = 0; i < 8; ++i)
#pragma unroll
            for (int j = 0; j < 8; ++j) s[i][j] = 0.f;

#pragma unroll 4
        for (int dd = 0; dd < 64; ++dd) {
            float a[8], b[8];
            *(float4*)&a[0] = *(const float4*)&Qs[dd * 128 + ty * 4];
            *(float4*)&a[4] = *(const float4*)&Qs[dd * 128 + 64 + ty * 4];
            *(float4*)&b[0] = *(const float4*)&Ks[dd * 128 + tx * 4];
            *(float4*)&b[4] = *(const float4*)&Ks[dd * 128 + 64 + tx * 4];
#pragma unroll
            for (int i = 0; i < 8; ++i)
#pragma unroll
                for (int j = 0; j < 8; ++j)
                    s[i][j] += a[i] * b[j];
        }

        const bool diag = (jt == it);
#pragma unroll
        for (int i = 0; i < 8; ++i) {
            const int rg = r0 + ((i < 4) ? (ty * 4 + i) : (60 + ty * 4 + i));
            if (diag) {
#pragma unroll
                for (int j = 0; j < 8; ++j) {
                    const int cg = c0 + ((j < 4) ? (tx * 4 + j) : (60 + tx * 4 + j));
                    if (cg > rg) s[i][j] = -1e30f;
                }
            }
            float mx = s[i][0];
#pragma unroll
            for (int j = 1; j < 8; ++j) mx = fmaxf(mx, s[i][j]);
            mx = fmaxf(mx, __shfl_xor_sync(0xffffffffu, mx, 1));
            mx = fmaxf(mx, __shfl_xor_sync(0xffffffffu, mx, 2));
            mx = fmaxf(mx, __shfl_xor_sync(0xffffffffu, mx, 4));
            mx = fmaxf(mx, __shfl_xor_sync(0xffffffffu, mx, 8));

            const float mnew = fmaxf(m[i], mx);
            const float corr = __expf(m[i] - mnew);
            float sum = 0.f;
#pragma unroll
            for (int j = 0; j < 8; ++j) {
                s[i][j] = __expf(s[i][j] - mnew);
                sum += s[i][j];
            }
            sum += __shfl_xor_sync(0xffffffffu, sum, 1);
            sum += __shfl_xor_sync(0xffffffffu, sum, 2);
            sum += __shfl_xor_sync(0xffffffffu, sum, 4);
            sum += __shfl_xor_sync(0xffffffffu, sum, 8);

            l[i] = l[i] * corr + sum;
            m[i] = mnew;
            o[i][0] *= corr; o[i][1] *= corr; o[i][2] *= corr; o[i][3] *= corr;
        }

#pragma unroll
        for (int j = 0; j < 8; ++j) {
            const int c = (j < 4) ? (tx * 4 + j) : (60 + tx * 4 + j);
            const int sw = pswz(c);
            *(float4*)&Ps[c * 128 + ((ty ^ sw) << 2)] =
                make_float4(s[0][j], s[1][j], s[2][j], s[3][j]);
            *(float4*)&Ps[c * 128 + (((ty + 16) ^ sw) << 2)] =
                make_float4(s[4][j], s[5][j], s[6][j], s[7][j]);
        }
        __syncthreads();

#pragma unroll 2
        for (int cc = 0; cc < 128; ++cc) {
            const int sw = pswz(cc);
            float a[8], bv[4];
            *(float4*)&a[0] = *(const float4*)&Ps[cc * 128 + ((ty ^ sw) << 2)];
            *(float4*)&a[4] = *(const float4*)&Ps[cc * 128 + (((ty + 16) ^ sw) << 2)];
            *(float4*)&bv[0] = *(const float4*)&Vs[cc * 64 + tx * 4];
#pragma unroll
            for (int i = 0; i < 8; ++i)
#pragma unroll
                for (int j = 0; j < 4; ++j)
                    o[i][j] += a[i] * bv[j];
        }
    }

    const int b = bh / NH, h = bh % NH;
#pragma unroll
    for (int i = 0; i < 8; ++i) {
        const int r = r0 + ((i < 4) ? (ty * 4 + i) : (60 + ty * 4 + i));
        const float inv = 1.0f / l[i];
        float4 v = make_float4(o[i][0] * inv, o[i][1] * inv,
                               o[i][2] * inv, o[i][3] * inv);
        *(float4*)&g_o[((size_t)b * SEQ + r) * CH + h * 64 + tx * 4] = v;
    }
}

// =====================================================================
// launch
// =====================================================================
extern "C" void kernel_launch(void* const* d_in, const int* in_sizes, int n_in,
                              void* d_out, int out_size)
{
    (void)in_sizes; (void)n_in; (void)out_size;
    const float* x      = (const float*)d_in[0];
    const float* w_qkv  = (const float*)d_in[1];
    const float* w_proj = (const float*)d_in[2];
    const float* b_proj = (const float*)d_in[3];
    float* out = (float*)d_out;

    cudaFuncSetAttribute((const void*)attn_kernel,
                         cudaFuncAttributeMaxDynamicSharedMemorySize, 163840);

    qkv_mma<<<dim3(18, 64), 256>>>(x, w_qkv);
    attn_kernel<<<dim3(16, 48), 256, 163840>>>();
    proj_mma<<<dim3(6, 64), 256>>>(w_proj, b_proj, out);
}

// round 4
// speedup vs baseline: 2.4086x; 1.8492x over previous
#include <cuda_runtime.h>
#include <cstdint>

// ---------------- problem constants ----------------
#define BSZ  4
#define SEQ  2048
#define CH   768
#define NH   12
#define HD   64
#define BHN  (BSZ*NH)          // 48

// ---------------- scratch (no cudaMalloc allowed) ----------------
__device__ float g_q[(size_t)BHN*SEQ*HD];   // [bh][n][d]
__device__ float g_k[(size_t)BHN*SEQ*HD];
__device__ float g_v[(size_t)BHN*SEQ*HD];
__device__ float g_o[(size_t)BSZ*SEQ*CH];   // [b*n][c] attention output

// ---------------- helpers ----------------
__device__ __forceinline__ uint32_t f2tf32(float x) {   // round-to-nearest tf32
    uint32_t u; asm("cvt.rna.tf32.f32 %0, %1;" : "=r"(u) : "f"(x)); return u;
}

// D += A(16x8,row) * B(8x8,col)  tf32
__device__ __forceinline__ void mma8(float* c, const uint32_t* a, const uint32_t* b) {
    asm("mma.sync.aligned.m16n8k8.row.col.f32.tf32.tf32.f32 "
        "{%0,%1,%2,%3}, {%4,%5,%6,%7}, {%8,%9}, {%0,%1,%2,%3};"
        : "+f"(c[0]), "+f"(c[1]), "+f"(c[2]), "+f"(c[3])
        : "r"(a[0]), "r"(a[1]), "r"(a[2]), "r"(a[3]), "r"(b[0]), "r"(b[1]));
}

// =====================================================================
// tf32 mma GEMM core (unchanged from R3)
// =====================================================================
__device__ __forceinline__ void gemm_core(const float* __restrict__ A,
                                          const float* __restrict__ B,
                                          int m0, int n0, int nstride,
                                          uint32_t* __restrict__ As,
                                          uint32_t* __restrict__ Bs,
                                          float acc[2][8][4])
{
    const int tid  = threadIdx.x;
    const int lane = tid & 31;
    const int wid  = tid >> 5;
    const int g    = lane >> 2;      // 0..7
    const int t    = lane & 3;       // 0..3
    const int wm   = (wid >> 1) * 32;
    const int wn   = (wid & 1) * 64;

    const int am = tid >> 2;
    const int ac = tid & 3;
    const int bk = tid >> 5;
    const int bu = tid & 31;

#pragma unroll
    for (int mt = 0; mt < 2; ++mt)
#pragma unroll
        for (int nt = 0; nt < 8; ++nt)
#pragma unroll
            for (int j = 0; j < 4; ++j) acc[mt][nt][j] = 0.f;

    const int NT = CH / 16;          // 48
    float4 ra[2], rb[2];

#pragma unroll
    for (int i = 0; i < 2; ++i) {
        ra[i] = *(const float4*)(A + (size_t)(m0 + am + i * 64) * CH + ac * 4);
        rb[i] = *(const float4*)(B + (size_t)(bk + i * 8) * nstride + n0 + bu * 4);
    }

    for (int kt = 0; kt < NT; ++kt) {
        const int buf = kt & 1;
        uint32_t* Ab = As + buf * 2048;
        uint32_t* Bb = Bs + buf * 2048;

        {
#pragma unroll
            for (int i = 0; i < 2; ++i) {
                const float v[4] = {ra[i].x, ra[i].y, ra[i].z, ra[i].w};
                const int m = am + i * 64;
#pragma unroll
                for (int s = 0; s < 4; ++s) {
                    const int comp = (s + ac) & 3;
                    const int k = ac * 4 + comp;
                    Ab[k * 128 + (m ^ (comp << 3))] = f2tf32(v[comp]);
                }
                const int kk = bk + i * 8;
                uint4 w = make_uint4(f2tf32(rb[i].x), f2tf32(rb[i].y),
                                     f2tf32(rb[i].z), f2tf32(rb[i].w));
                *(uint4*)&Bb[kk * 128 + ((bu * 4) ^ ((kk & 3) << 3))] = w;
            }
        }
        __syncthreads();

        if (kt + 1 < NT) {
            const int k0 = (kt + 1) * 16;
#pragma unroll
            for (int i = 0; i < 2; ++i) {
                ra[i] = *(const float4*)(A + (size_t)(m0 + am + i * 64) * CH + k0 + ac * 4);
                rb[i] = *(const float4*)(B + (size_t)(k0 + bk + i * 8) * nstride + n0 + bu * 4);
            }
        }

#pragma unroll
        for (int ks = 0; ks < 2; ++ks) {
            const int krow = ks * 8 + t;
            const int sw = t << 3;
            uint32_t afr[2][4];
#pragma unroll
            for (int mt = 0; mt < 2; ++mt) {
                const int mb = wm + mt * 16 + g;
                afr[mt][0] = Ab[krow * 128 + (mb ^ sw)];
                afr[mt][1] = Ab[krow * 128 + ((mb + 8) ^ sw)];
                afr[mt][2] = Ab[(krow + 4) * 128 + (mb ^ sw)];
                afr[mt][3] = Ab[(krow + 4) * 128 + ((mb + 8) ^ sw)];
            }
#pragma unroll
            for (int nt = 0; nt < 8; ++nt) {
                const int nb = wn + nt * 8 + g;
                uint32_t bfr[2];
                bfr[0] = Bb[krow * 128 + (nb ^ sw)];
                bfr[1] = Bb[(krow + 4) * 128 + (nb ^ sw)];
                mma8(acc[0][nt], afr[0], bfr);
                mma8(acc[1][nt], afr[1], bfr);
            }
        }
        __syncthreads();
    }
}

// =====================================================================
// GEMM 1: qkv = x @ w_qkv, scatter epilogue into g_q/g_k/g_v
// =====================================================================
__global__ __launch_bounds__(256, 2) void qkv_mma(const float* __restrict__ x,
                                                  const float* __restrict__ w)
{
    __shared__ uint32_t As[2 * 2048];
    __shared__ uint32_t Bs[2 * 2048];
    float acc[2][8][4];

    const int m0 = blockIdx.y * 128;
    const int n0 = blockIdx.x * 128;
    gemm_core(x, w, m0, n0, 3 * CH, As, Bs, acc);

    const int tid = threadIdx.x;
    const int lane = tid & 31, wid = tid >> 5;
    const int g = lane >> 2, t = lane & 3;
    const int wm = (wid >> 1) * 32, wn = (wid & 1) * 64;

    const int t3 = blockIdx.x / 6;               // 0:q 1:k 2:v
    const int nb = (blockIdx.x % 6) * 128;
    float* dst = (t3 == 0) ? g_q : (t3 == 1) ? g_k : g_v;

#pragma unroll
    for (int mt = 0; mt < 2; ++mt) {
        const int r = m0 + wm + mt * 16 + g;
        const int b = r >> 11, n = r & (SEQ - 1);
#pragma unroll
        for (int nt = 0; nt < 8; ++nt) {
            const int cb = nb + wn + nt * 8 + 2 * t;
            const int h = cb >> 6, d = cb & 63;
            float* p = dst + (((size_t)b * NH + h) * SEQ + n) * HD + d;
            *(float2*)p = make_float2(acc[mt][nt][0], acc[mt][nt][1]);
            *(float2*)(p + 8 * HD) = make_float2(acc[mt][nt][2], acc[mt][nt][3]);
        }
    }
}

// =====================================================================
// GEMM 2: out = g_o @ w_proj + bias
// =====================================================================
__global__ __launch_bounds__(256, 2) void proj_mma(const float* __restrict__ w,
                                                   const float* __restrict__ bias,
                                                   float* __restrict__ out)
{
    __shared__ uint32_t As[2 * 2048];
    __shared__ uint32_t Bs[2 * 2048];
    float acc[2][8][4];

    const int m0 = blockIdx.y * 128;
    const int n0 = blockIdx.x * 128;
    gemm_core(g_o, w, m0, n0, CH, As, Bs, acc);

    const int tid = threadIdx.x;
    const int lane = tid & 31, wid = tid >> 5;
    const int g = lane >> 2, t = lane & 3;
    const int wm = (wid >> 1) * 32, wn = (wid & 1) * 64;

#pragma unroll
    for (int mt = 0; mt < 2; ++mt) {
        const int r = m0 + wm + mt * 16 + g;
#pragma unroll
        for (int nt = 0; nt < 8; ++nt) {
            const int col = n0 + wn + nt * 8 + 2 * t;
            const float2 bv = *(const float2*)(bias + col);
            float* p = out + (size_t)r * CH + col;
            *(float2*)p = make_float2(acc[mt][nt][0] + bv.x, acc[mt][nt][1] + bv.y);
            *(float2*)(p + 8 * CH) = make_float2(acc[mt][nt][2] + bv.x,
                                                 acc[mt][nt][3] + bv.y);
        }
    }
}

// =====================================================================
// Flash attention (causal) on mma.sync tf32.
// Block = 128 q-rows of one (b,h); streams 128-wide KV tiles.
// 8 warps, warp = 16 q-rows x full 128 kv cols -> softmax rows live in
// one warp (shfl over t-quad only).
// smem (uint32): Qs[64][128] (d-major, scaled, tf32), Ks[64][128],
//                Vs[128][64], Ps[128][128] (kv-major P, tf32). 160 KB.
// Swizzle everywhere: elem (k, m) at [k*W + (m ^ ((k&3)<<3))].
// =====================================================================
__global__ __launch_bounds__(256, 1) void attn_mma()
{
    extern __shared__ uint32_t sm[];
    uint32_t* Qs = sm;                // 8192
    uint32_t* Ks = sm + 8192;         // 8192
    uint32_t* Vs = sm + 16384;        // 8192
    uint32_t* Ps = sm + 24576;        // 16384

    const int bh = blockIdx.y;
    const int it = (gridDim.x - 1) - blockIdx.x;   // longest first
    const int r0 = it * 128;

    const float* Qg = g_q + (size_t)bh * (SEQ * HD);
    const float* Kg = g_k + (size_t)bh * (SEQ * HD);
    const float* Vg = g_v + (size_t)bh * (SEQ * HD);

    const int tid  = threadIdx.x;
    const int lane = tid & 31;
    const int wid  = tid >> 5;
    const int g    = lane >> 2;       // 0..7
    const int t    = lane & 3;        // 0..3
    const int wm   = wid * 16;        // warp q-row base (local)

    // ---- load Q tile transposed [d][row], scaled, tf32 ----
    {
        const int row = tid >> 1, half = tid & 1;
        const float* qp = Qg + (size_t)(r0 + row) * HD + half * 32;
#pragma unroll
        for (int j = 0; j < 8; ++j) {
            float4 v = *(const float4*)(qp + j * 4);
            const float vv[4] = {v.x, v.y, v.z, v.w};
#pragma unroll
            for (int s = 0; s < 4; ++s) {
                const int d = half * 32 + j * 4 + s;
                Qs[d * 128 + (row ^ ((d & 3) << 3))] = f2tf32(vv[s] * 0.125f);
            }
        }
    }

    float o[8][4];
    float m0r = -1e30f, m1r = -1e30f, l0 = 0.f, l1 = 0.f;
#pragma unroll
    for (int nt = 0; nt < 8; ++nt)
        o[nt][0] = o[nt][1] = o[nt][2] = o[nt][3] = 0.f;

    for (int jt = 0; jt <= it; ++jt) {
        const int c0 = jt * 128;
        __syncthreads();   // prev P@V done reading Ks/Vs/Ps; Q visible (1st iter)

        // ---- load K transposed [d][col] tf32 ----
        {
            const int col = tid >> 1, half = tid & 1;
            const float* kp = Kg + (size_t)(c0 + col) * HD + half * 32;
#pragma unroll
            for (int j = 0; j < 8; ++j) {
                float4 v = *(const float4*)(kp + j * 4);
                const float vv[4] = {v.x, v.y, v.z, v.w};
#pragma unroll
                for (int s = 0; s < 4; ++s) {
                    const int d = half * 32 + j * 4 + s;
                    Ks[d * 128 + (col ^ ((d & 3) << 3))] = f2tf32(vv[s]);
                }
            }
            // ---- load V [kv][d] tf32, swizzled ----
#pragma unroll
            for (int i = 0; i < 8; ++i) {
                const int f = tid + i * 256;
                const int kv = f >> 4, c4 = (f & 15) * 4;
                float4 v = *(const float4*)(Vg + (size_t)(c0 + kv) * HD + c4);
                uint4 w = make_uint4(f2tf32(v.x), f2tf32(v.y),
                                     f2tf32(v.z), f2tf32(v.w));
                *(uint4*)&Vs[kv * 64 + (c4 ^ ((kv & 3) << 3))] = w;
            }
        }
        __syncthreads();

        // ---- S = Q @ K^T : warp computes 16 rows x 128 cols ----
        float s[16][4];
#pragma unroll
        for (int nt = 0; nt < 16; ++nt)
            s[nt][0] = s[nt][1] = s[nt][2] = s[nt][3] = 0.f;

#pragma unroll
        for (int ks = 0; ks < 8; ++ks) {
            const int krow = ks * 8 + t;
            const int sw = t << 3;
            uint32_t a[4];
            a[0] = Qs[krow * 128 + ((wm + g) ^ sw)];
            a[1] = Qs[krow * 128 + ((wm + g + 8) ^ sw)];
            a[2] = Qs[(krow + 4) * 128 + ((wm + g) ^ sw)];
            a[3] = Qs[(krow + 4) * 128 + ((wm + g + 8) ^ sw)];
#pragma unroll
            for (int nt = 0; nt < 16; ++nt) {
                const int nb = nt * 8 + g;
                uint32_t b[2];
                b[0] = Ks[krow * 128 + (nb ^ sw)];
                b[1] = Ks[(krow + 4) * 128 + (nb ^ sw)];
                mma8(s[nt], a, b);
            }
        }

        // ---- causal mask (diag tile) + online softmax ----
        if (jt == it) {
            const int rg0 = r0 + wm + g, rg1 = rg0 + 8;
#pragma unroll
            for (int nt = 0; nt < 16; ++nt) {
                const int cg = c0 + nt * 8 + 2 * t;
                if (cg     > rg0) s[nt][0] = -1e30f;
                if (cg + 1 > rg0) s[nt][1] = -1e30f;
                if (cg     > rg1) s[nt][2] = -1e30f;
                if (cg + 1 > rg1) s[nt][3] = -1e30f;
            }
        }

        float mx0 = -1e30f, mx1 = -1e30f;
#pragma unroll
        for (int nt = 0; nt < 16; ++nt) {
            mx0 = fmaxf(mx0, fmaxf(s[nt][0], s[nt][1]));
            mx1 = fmaxf(mx1, fmaxf(s[nt][2], s[nt][3]));
        }
        mx0 = fmaxf(mx0, __shfl_xor_sync(0xffffffffu, mx0, 1));
        mx0 = fmaxf(mx0, __shfl_xor_sync(0xffffffffu, mx0, 2));
        mx1 = fmaxf(mx1, __shfl_xor_sync(0xffffffffu, mx1, 1));
        mx1 = fmaxf(mx1, __shfl_xor_sync(0xffffffffu, mx1, 2));

        const float mn0 = fmaxf(m0r, mx0);
        const float mn1 = fmaxf(m1r, mx1);
        const float cr0 = __expf(m0r - mn0);
        const float cr1 = __expf(m1r - mn1);

        float sum0 = 0.f, sum1 = 0.f;
#pragma unroll
        for (int nt = 0; nt < 16; ++nt) {
            s[nt][0] = __expf(s[nt][0] - mn0);
            s[nt][1] = __expf(s[nt][1] - mn0);
            s[nt][2] = __expf(s[nt][2] - mn1);
            s[nt][3] = __expf(s[nt][3] - mn1);
            sum0 += s[nt][0] + s[nt][1];
            sum1 += s[nt][2] + s[nt][3];
        }
        sum0 += __shfl_xor_sync(0xffffffffu, sum0, 1);
        sum0 += __shfl_xor_sync(0xffffffffu, sum0, 2);
        sum1 += __shfl_xor_sync(0xffffffffu, sum1, 1);
        sum1 += __shfl_xor_sync(0xffffffffu, sum1, 2);

        l0 = l0 * cr0 + sum0;  m0r = mn0;
        l1 = l1 * cr1 + sum1;  m1r = mn1;
#pragma unroll
        for (int nt = 0; nt < 8; ++nt) {
            o[nt][0] *= cr0; o[nt][1] *= cr0;
            o[nt][2] *= cr1; o[nt][3] *= cr1;
        }

        // ---- store P to Ps [kv][qrow], tf32, swizzled ----
#pragma unroll
        for (int nt = 0; nt < 16; ++nt) {
            const int c = nt * 8 + 2 * t;
            const int sw0 = (c & 3) << 3;
            const int sw1 = ((c + 1) & 3) << 3;
            Ps[c * 128 + ((wm + g) ^ sw0)]           = f2tf32(s[nt][0]);
            Ps[(c + 1) * 128 + ((wm + g) ^ sw1)]     = f2tf32(s[nt][1]);
            Ps[c * 128 + ((wm + g + 8) ^ sw0)]       = f2tf32(s[nt][2]);
            Ps[(c + 1) * 128 + ((wm + g + 8) ^ sw1)] = f2tf32(s[nt][3]);
        }
        __syncthreads();

        // ---- O += P @ V : warp 16 rows x 64 d ----
#pragma unroll
        for (int ks = 0; ks < 16; ++ks) {
            const int krow = ks * 8 + t;
            const int sw = t << 3;
            uint32_t a[4];
            a[0] = Ps[krow * 128 + ((wm + g) ^ sw)];
            a[1] = Ps[krow * 128 + ((wm + g + 8) ^ sw)];
            a[2] = Ps[(krow + 4) * 128 + ((wm + g) ^ sw)];
            a[3] = Ps[(krow + 4) * 128 + ((wm + g + 8) ^ sw)];
#pragma unroll
            for (int nt = 0; nt < 8; ++nt) {
                const int nb = nt * 8 + g;
                uint32_t b[2];
                b[0] = Vs[krow * 64 + (nb ^ sw)];
                b[1] = Vs[(krow + 4) * 64 + (nb ^ sw)];
                mma8(o[nt], a, b);
            }
        }
    }

    // ---- normalize + write to g_o [b*n][c] ----
    const int b = bh / NH, h = bh % NH;
    const float inv0 = 1.0f / l0, inv1 = 1.0f / l1;
    const int row0 = r0 + wm + g;
#pragma unroll
    for (int nt = 0; nt < 8; ++nt) {
        const int col = h * 64 + nt * 8 + 2 * t;
        *(float2*)&g_o[((size_t)b * SEQ + row0) * CH + col] =
            make_float2(o[nt][0] * inv0, o[nt][1] * inv0);
        *(float2*)&g_o[((size_t)b * SEQ + row0 + 8) * CH + col] =
            make_float2(o[nt][2] * inv1, o[nt][3] * inv1);
    }
}

// =====================================================================
// launch
// =====================================================================
extern "C" void kernel_launch(void* const* d_in, const int* in_sizes, int n_in,
                              void* d_out, int out_size)
{
    (void)in_sizes; (void)n_in; (void)out_size;
    const float* x      = (const float*)d_in[0];
    const float* w_qkv  = (const float*)d_in[1];
    const float* w_proj = (const float*)d_in[2];
    const float* b_proj = (const float*)d_in[3];
    float* out = (float*)d_out;

    cudaFuncSetAttribute((const void*)attn_mma,
                         cudaFuncAttributeMaxDynamicSharedMemorySize, 163840);

    qkv_mma<<<dim3(18, 64), 256>>>(x, w_qkv);
    attn_mma<<<dim3(16, 48), 256, 163840>>>();
    proj_mma<<<dim3(6, 64), 256>>>(w_proj, b_proj, out);
}

// round 5
// speedup vs baseline: 2.4495x; 1.0170x over previous
#include <cuda_runtime.h>
#include <cstdint>

// ---------------- problem constants ----------------
#define BSZ  4
#define SEQ  2048
#define CH   768
#define NH   12
#define HD   64
#define BHN  (BSZ*NH)          // 48

// ---------------- scratch (no cudaMalloc allowed) ----------------
__device__ float g_q[(size_t)BHN*SEQ*HD];   // [bh][n][d]
__device__ float g_k[(size_t)BHN*SEQ*HD];
__device__ float g_v[(size_t)BHN*SEQ*HD];
__device__ float g_o[(size_t)BSZ*SEQ*CH];   // [b*n][c]

// ---------------- helpers ----------------
__device__ __forceinline__ uint32_t f2tf32(float x) {
    uint32_t u; asm("cvt.rna.tf32.f32 %0, %1;" : "=r"(u) : "f"(x)); return u;
}
__device__ __forceinline__ uint32_t fsw(uint32_t x) { return x ^ (x >> 2); }

// D += A(16x8,row) * B(8x8,col)  tf32
__device__ __forceinline__ void mma8(float* c, const uint32_t* a, const uint32_t* b) {
    asm("mma.sync.aligned.m16n8k8.row.col.f32.tf32.tf32.f32 "
        "{%0,%1,%2,%3}, {%4,%5,%6,%7}, {%8,%9}, {%0,%1,%2,%3};"
        : "+f"(c[0]), "+f"(c[1]), "+f"(c[2]), "+f"(c[3])
        : "r"(a[0]), "r"(a[1]), "r"(a[2]), "r"(a[3]), "r"(b[0]), "r"(b[1]));
}
__device__ __forceinline__ float fidx(const float4& v, int s) {
    return (s == 0) ? v.x : (s == 1) ? v.y : (s == 2) ? v.z : v.w;
}

// Paired-tile format PT(RS): logical (k, col); q = (k>>3)*4 + (k&3),
// e = (k>>2)&1; word addr = q*RS + 2*fsw(col ^ ((k&3)<<2)) + e.
// Fragment (k=ks*8+t, k+4): one LDS.64 at e=0.

// =====================================================================
// GEMM core: C[128x128] = A[128x768] * B[768x128slice], PT(272) tiles.
// =====================================================================
__device__ __forceinline__ void gemm_store(uint32_t* __restrict__ As,
                                           uint32_t* __restrict__ Bs,
                                           int BO,
                                           const uint32_t aSt[2][4],
                                           const uint32_t bSt[4],
                                           const float4 ra[2],
                                           const float4& rbl, const float4& rbh)
{
#pragma unroll
    for (int i = 0; i < 2; ++i)
#pragma unroll
        for (int s = 0; s < 4; ++s)
            As[BO + aSt[i][s]] = f2tf32(fidx(ra[i], s));
#pragma unroll
    for (int s = 0; s < 4; ++s)
        *(uint2*)&Bs[BO + bSt[s]] = make_uint2(f2tf32(fidx(rbl, s)),
                                               f2tf32(fidx(rbh, s)));
}

__device__ __forceinline__ void gemm_comp(const uint32_t* __restrict__ As,
                                          const uint32_t* __restrict__ Bs,
                                          int BO,
                                          const uint32_t aFr[2][2],
                                          const uint32_t bFr[8],
                                          float acc[2][8][4])
{
#pragma unroll
    for (int ks = 0; ks < 2; ++ks) {
        uint2 aw00 = *(const uint2*)&As[BO + ks * 1088 + aFr[0][0]];
        uint2 aw01 = *(const uint2*)&As[BO + ks * 1088 + aFr[0][1]];
        uint2 aw10 = *(const uint2*)&As[BO + ks * 1088 + aFr[1][0]];
        uint2 aw11 = *(const uint2*)&As[BO + ks * 1088 + aFr[1][1]];
        uint32_t a0[4] = {aw00.x, aw01.x, aw00.y, aw01.y};
        uint32_t a1[4] = {aw10.x, aw11.x, aw10.y, aw11.y};
#pragma unroll
        for (int nt = 0; nt < 8; ++nt) {
            uint2 bw = *(const uint2*)&Bs[BO + ks * 1088 + bFr[nt]];
            uint32_t b[2] = {bw.x, bw.y};
            mma8(acc[0][nt], a0, b);
            mma8(acc[1][nt], a1, b);
        }
    }
}

__device__ __forceinline__ void gemm_core(const float* __restrict__ A,
                                          const float* __restrict__ B,
                                          int m0, int n0, int nstride,
                                          uint32_t* __restrict__ As,
                                          uint32_t* __restrict__ Bs,
                                          float acc[2][8][4])
{
    const int tid  = threadIdx.x;
    const int lane = tid & 31;
    const int wid  = tid >> 5;
    const int g    = lane >> 2;
    const int t    = lane & 3;
    const int wm   = (wid >> 1) * 32;
    const int wn   = (wid & 1) * 64;

    const int am = tid >> 2;             // A gmem row 0..63 (+64)
    const int ac = tid & 3;              // A k-group
    const int klo = (wid >> 2) * 8 + (wid & 3);   // B pair row (warp-owned)

    uint32_t aSt[2][4], bSt[4], aFr[2][2], bFr[8];
#pragma unroll
    for (int i = 0; i < 2; ++i)
#pragma unroll
        for (int s = 0; s < 4; ++s)
            aSt[i][s] = (uint32_t)((4 * (ac >> 1) + s) * 272
                       + 2 * fsw((am + 64 * i) ^ (s << 2)) + (ac & 1));
#pragma unroll
    for (int s = 0; s < 4; ++s)
        bSt[s] = (uint32_t)(wid * 272 + 2 * fsw((4 * lane + s) ^ ((wid & 3) << 2)));
#pragma unroll
    for (int mt = 0; mt < 2; ++mt)
#pragma unroll
        for (int h = 0; h < 2; ++h)
            aFr[mt][h] = (uint32_t)(t * 272
                        + 2 * fsw((wm + mt * 16 + g + 8 * h) ^ (t << 2)));
#pragma unroll
    for (int nt = 0; nt < 8; ++nt)
        bFr[nt] = (uint32_t)(t * 272 + 2 * fsw((wn + nt * 8 + g) ^ (t << 2)));

#pragma unroll
    for (int mt = 0; mt < 2; ++mt)
#pragma unroll
        for (int nt = 0; nt < 8; ++nt)
#pragma unroll
            for (int j = 0; j < 4; ++j) acc[mt][nt][j] = 0.f;

    const int NT = CH / 16;      // 48 (even)
    float4 ra[2], rbl, rbh;

    // prologue: kt = 0
    ra[0] = *(const float4*)(A + (size_t)(m0 + am) * CH + ac * 4);
    ra[1] = *(const float4*)(A + (size_t)(m0 + am + 64) * CH + ac * 4);
    rbl = *(const float4*)(B + (size_t)klo * nstride + n0 + lane * 4);
    rbh = *(const float4*)(B + (size_t)(klo + 4) * nstride + n0 + lane * 4);
    gemm_store(As, Bs, 0, aSt, bSt, ra, rbl, rbh);

    for (int kt = 0; kt < NT; kt += 2) {
        __syncthreads();
        {   // prefetch kt+1 (kt+1 <= 47 always valid inside loop)
            const int k0 = (kt + 1) * 16;
            ra[0] = *(const float4*)(A + (size_t)(m0 + am) * CH + k0 + ac * 4);
            ra[1] = *(const float4*)(A + (size_t)(m0 + am + 64) * CH + k0 + ac * 4);
            rbl = *(const float4*)(B + (size_t)(k0 + klo) * nstride + n0 + lane * 4);
            rbh = *(const float4*)(B + (size_t)(k0 + klo + 4) * nstride + n0 + lane * 4);
        }
        gemm_comp(As, Bs, 0, aFr, bFr, acc);
        gemm_store(As, Bs, 2176, aSt, bSt, ra, rbl, rbh);
        __syncthreads();
        if (kt + 2 < NT) {
            const int k0 = (kt + 2) * 16;
            ra[0] = *(const float4*)(A + (size_t)(m0 + am) * CH + k0 + ac * 4);
            ra[1] = *(const float4*)(A + (size_t)(m0 + am + 64) * CH + k0 + ac * 4);
            rbl = *(const float4*)(B + (size_t)(k0 + klo) * nstride + n0 + lane * 4);
            rbh = *(const float4*)(B + (size_t)(k0 + klo + 4) * nstride + n0 + lane * 4);
        }
        gemm_comp(As, Bs, 2176, aFr, bFr, acc);
        if (kt + 2 < NT)
            gemm_store(As, Bs, 0, aSt, bSt, ra, rbl, rbh);
    }
}

// =====================================================================
// GEMM 1: qkv = x @ w_qkv, scatter into g_q/g_k/g_v
// =====================================================================
__global__ __launch_bounds__(256, 2) void qkv_mma(const float* __restrict__ x,
                                                  const float* __restrict__ w)
{
    __shared__ __align__(16) uint32_t As[2 * 2176];
    __shared__ __align__(16) uint32_t Bs[2 * 2176];
    float acc[2][8][4];

    const int m0 = blockIdx.y * 128;
    const int n0 = blockIdx.x * 128;
    gemm_core(x, w, m0, n0, 3 * CH, As, Bs, acc);

    const int tid = threadIdx.x;
    const int lane = tid & 31, wid = tid >> 5;
    const int g = lane >> 2, t = lane & 3;
    const int wm = (wid >> 1) * 32, wn = (wid & 1) * 64;

    const int t3 = blockIdx.x / 6;
    const int nb = (blockIdx.x % 6) * 128;
    float* dst = (t3 == 0) ? g_q : (t3 == 1) ? g_k : g_v;

#pragma unroll
    for (int mt = 0; mt < 2; ++mt) {
        const int r = m0 + wm + mt * 16 + g;
        const int b = r >> 11, n = r & (SEQ - 1);
#pragma unroll
        for (int nt = 0; nt < 8; ++nt) {
            const int cb = nb + wn + nt * 8 + 2 * t;
            const int h = cb >> 6, d = cb & 63;
            float* p = dst + (((size_t)b * NH + h) * SEQ + n) * HD + d;
            *(float2*)p = make_float2(acc[mt][nt][0], acc[mt][nt][1]);
            *(float2*)(p + 8 * HD) = make_float2(acc[mt][nt][2], acc[mt][nt][3]);
        }
    }
}

// =====================================================================
// GEMM 2: out = g_o @ w_proj + bias
// =====================================================================
__global__ __launch_bounds__(256, 2) void proj_mma(const float* __restrict__ w,
                                                   const float* __restrict__ bias,
                                                   float* __restrict__ out)
{
    __shared__ __align__(16) uint32_t As[2 * 2176];
    __shared__ __align__(16) uint32_t Bs[2 * 2176];
    float acc[2][8][4];

    const int m0 = blockIdx.y * 128;
    const int n0 = blockIdx.x * 128;
    gemm_core(g_o, w, m0, n0, CH, As, Bs, acc);

    const int tid = threadIdx.x;
    const int lane = tid & 31, wid = tid >> 5;
    const int g = lane >> 2, t = lane & 3;
    const int wm = (wid >> 1) * 32, wn = (wid & 1) * 64;

#pragma unroll
    for (int mt = 0; mt < 2; ++mt) {
        const int r = m0 + wm + mt * 16 + g;
#pragma unroll
        for (int nt = 0; nt < 8; ++nt) {
            const int col = n0 + wn + nt * 8 + 2 * t;
            const float2 bv = *(const float2*)(bias + col);
            float* p = out + (size_t)r * CH + col;
            *(float2*)p = make_float2(acc[mt][nt][0] + bv.x, acc[mt][nt][1] + bv.y);
            *(float2*)(p + 8 * CH) = make_float2(acc[mt][nt][2] + bv.x,
                                                 acc[mt][nt][3] + bv.y);
        }
    }
}

// =====================================================================
// Flash attention (causal), mma tf32 with PT layouts.
// smem words: Qs PT(272,q0..31) @0 (8704), Ks @8704 (8704),
//             Vs PT(144,q0..63) @17408 (9216), Ps PT(272,q0..63) @26624 (17408)
// total 44032 words = 176128 B.
// =====================================================================
#define QS_O 0
#define KS_O 8704
#define VS_O 17408
#define PS_O 26624

__global__ __launch_bounds__(256, 1) void attn_mma()
{
    extern __shared__ __align__(16) uint32_t sm[];

    const int bh = blockIdx.y;
    const int it = (gridDim.x - 1) - blockIdx.x;
    const int r0 = it * 128;

    const float* Qg = g_q + (size_t)bh * (SEQ * HD);
    const float* Kg = g_k + (size_t)bh * (SEQ * HD);
    const float* Vg = g_v + (size_t)bh * (SEQ * HD);

    const int tid  = threadIdx.x;
    const int lane = tid & 31;
    const int wid  = tid >> 5;
    const int g    = lane >> 2;
    const int t    = lane & 3;
    const int wm   = wid * 16;

    // ---- precomputed fragment / store addresses ----
    uint32_t qaF[2], paF[2], vbF[8], kbF[16], pSt[2][2];
#pragma unroll
    for (int h = 0; h < 2; ++h) {
        const uint32_t x = 2 * fsw((wm + g + 8 * h) ^ (t << 2));
        qaF[h] = QS_O + t * 272 + x;
        paF[h] = PS_O + t * 272 + x;
    }
#pragma unroll
    for (int nt = 0; nt < 16; ++nt)
        kbF[nt] = KS_O + t * 272 + 2 * fsw((nt * 8 + g) ^ (t << 2));
#pragma unroll
    for (int nt = 0; nt < 8; ++nt)
        vbF[nt] = VS_O + t * 144 + 2 * fsw((nt * 8 + g) ^ (t << 2));
#pragma unroll
    for (int b = 0; b < 2; ++b) {
        const int c3 = (2 * t + b) & 3;
        const int e  = (2 * t + b) >> 2;
#pragma unroll
        for (int rh = 0; rh < 2; ++rh)
            pSt[b][rh] = PS_O + c3 * 272
                       + 2 * fsw((wm + g + 8 * rh) ^ (c3 << 2)) + e;
    }

    // ---- load Q tile into PT(272), scaled, tf32 ----
    {
        const int row = tid >> 1, half = tid & 1;
        const float* qp = Qg + (size_t)(r0 + row) * HD + half * 32;
#pragma unroll
        for (int j = 0; j < 8; ++j) {
            float4 v = *(const float4*)(qp + j * 4);
            const int d0 = half * 32 + 4 * j;
            const int qb = (d0 >> 3) * 4;
            const int e  = (d0 >> 2) & 1;
#pragma unroll
            for (int s = 0; s < 4; ++s)
                sm[QS_O + (qb + s) * 272 + 2 * fsw(row ^ (s << 2)) + e] =
                    f2tf32(fidx(v, s) * 0.125f);
        }
    }

    float o[8][4];
    float m0r = -1e30f, m1r = -1e30f, l0 = 0.f, l1 = 0.f;
#pragma unroll
    for (int nt = 0; nt < 8; ++nt)
        o[nt][0] = o[nt][1] = o[nt][2] = o[nt][3] = 0.f;

    for (int jt = 0; jt <= it; ++jt) {
        const int c0 = jt * 128;
        __syncthreads();

        // ---- load K into PT(272) ----
        {
            const int row = tid >> 1, half = tid & 1;
            const float* kp = Kg + (size_t)(c0 + row) * HD + half * 32;
#pragma unroll
            for (int j = 0; j < 8; ++j) {
                float4 v = *(const float4*)(kp + j * 4);
                const int d0 = half * 32 + 4 * j;
                const int qb = (d0 >> 3) * 4;
                const int e  = (d0 >> 2) & 1;
#pragma unroll
                for (int s = 0; s < 4; ++s)
                    sm[KS_O + (qb + s) * 272 + 2 * fsw(row ^ (s << 2)) + e] =
                        f2tf32(fidx(v, s));
            }
        }
        // ---- load V into PT(144): thread owns pair-row q=tid>>2, 16 d ----
        {
            const int q  = tid >> 2;
            const int dl = (tid & 3) * 16;
            const int kvlo = (q >> 2) * 8 + (q & 3);
            const float* vl = Vg + (size_t)(c0 + kvlo) * HD + dl;
            const float* vh = vl + 4 * HD;
#pragma unroll
            for (int j = 0; j < 4; ++j) {
                float4 a4 = *(const float4*)(vl + 4 * j);
                float4 b4 = *(const float4*)(vh + 4 * j);
#pragma unroll
                for (int s = 0; s < 4; ++s) {
                    const int d = dl + 4 * j + s;
                    *(uint2*)&sm[VS_O + q * 144 + 2 * fsw(d ^ ((q & 3) << 2))] =
                        make_uint2(f2tf32(fidx(a4, s)), f2tf32(fidx(b4, s)));
                }
            }
        }
        __syncthreads();

        // ---- S = Q @ K^T : 16 rows x 128 cols per warp ----
        float s[16][4];
#pragma unroll
        for (int nt = 0; nt < 16; ++nt)
            s[nt][0] = s[nt][1] = s[nt][2] = s[nt][3] = 0.f;

#pragma unroll
        for (int ks = 0; ks < 8; ++ks) {
            uint2 aw0 = *(const uint2*)&sm[ks * 1088 + qaF[0]];
            uint2 aw1 = *(const uint2*)&sm[ks * 1088 + qaF[1]];
            uint32_t a[4] = {aw0.x, aw1.x, aw0.y, aw1.y};
#pragma unroll
            for (int nt = 0; nt < 16; ++nt) {
                uint2 bw = *(const uint2*)&sm[ks * 1088 + kbF[nt]];
                uint32_t b[2] = {bw.x, bw.y};
                mma8(s[nt], a, b);
            }
        }

        // ---- causal mask + online softmax ----
        if (jt == it) {
            const int rg0 = r0 + wm + g, rg1 = rg0 + 8;
#pragma unroll
            for (int nt = 0; nt < 16; ++nt) {
                const int cg = c0 + nt * 8 + 2 * t;
                if (cg     > rg0) s[nt][0] = -1e30f;
                if (cg + 1 > rg0) s[nt][1] = -1e30f;
                if (cg     > rg1) s[nt][2] = -1e30f;
                if (cg + 1 > rg1) s[nt][3] = -1e30f;
            }
        }

        float mx0 = -1e30f, mx1 = -1e30f;
#pragma unroll
        for (int nt = 0; nt < 16; ++nt) {
            mx0 = fmaxf(mx0, fmaxf(s[nt][0], s[nt][1]));
            mx1 = fmaxf(mx1, fmaxf(s[nt][2], s[nt][3]));
        }
        mx0 = fmaxf(mx0, __shfl_xor_sync(0xffffffffu, mx0, 1));
        mx0 = fmaxf(mx0, __shfl_xor_sync(0xffffffffu, mx0, 2));
        mx1 = fmaxf(mx1, __shfl_xor_sync(0xffffffffu, mx1, 1));
        mx1 = fmaxf(mx1, __shfl_xor_sync(0xffffffffu, mx1, 2));

        const float mn0 = fmaxf(m0r, mx0);
        const float mn1 = fmaxf(m1r, mx1);
        const float cr0 = __expf(m0r - mn0);
        const float cr1 = __expf(m1r - mn1);

        float sum0 = 0.f, sum1 = 0.f;
#pragma unroll
        for (int nt = 0; nt < 16; ++nt) {
            s[nt][0] = __expf(s[nt][0] - mn0);
            s[nt][1] = __expf(s[nt][1] - mn0);
            s[nt][2] = __expf(s[nt][2] - mn1);
            s[nt][3] = __expf(s[nt][3] - mn1);
            sum0 += s[nt][0] + s[nt][1];
            sum1 += s[nt][2] + s[nt][3];
        }
        sum0 += __shfl_xor_sync(0xffffffffu, sum0, 1);
        sum0 += __shfl_xor_sync(0xffffffffu, sum0, 2);
        sum1 += __shfl_xor_sync(0xffffffffu, sum1, 1);
        sum1 += __shfl_xor_sync(0xffffffffu, sum1, 2);

        l0 = l0 * cr0 + sum0;  m0r = mn0;
        l1 = l1 * cr1 + sum1;  m1r = mn1;
#pragma unroll
        for (int nt = 0; nt < 8; ++nt) {
            o[nt][0] *= cr0; o[nt][1] *= cr0;
            o[nt][2] *= cr1; o[nt][3] *= cr1;
        }

        // ---- store P into PT(272) (conflict-free) ----
#pragma unroll
        for (int nt = 0; nt < 16; ++nt) {
            sm[nt * 1088 + pSt[0][0]] = f2tf32(s[nt][0]);
            sm[nt * 1088 + pSt[1][0]] = f2tf32(s[nt][1]);
            sm[nt * 1088 + pSt[0][1]] = f2tf32(s[nt][2]);
            sm[nt * 1088 + pSt[1][1]] = f2tf32(s[nt][3]);
        }
        __syncthreads();

        // ---- O += P @ V ----
#pragma unroll
        for (int ks = 0; ks < 16; ++ks) {
            uint2 aw0 = *(const uint2*)&sm[ks * 1088 + paF[0]];
            uint2 aw1 = *(const uint2*)&sm[ks * 1088 + paF[1]];
            uint32_t a[4] = {aw0.x, aw1.x, aw0.y, aw1.y};
#pragma unroll
            for (int nt = 0; nt < 8; ++nt) {
                uint2 bw = *(const uint2*)&sm[ks * 576 + vbF[nt]];
                uint32_t b[2] = {bw.x, bw.y};
                mma8(o[nt], a, b);
            }
        }
    }

    // ---- normalize + write to g_o ----
    const int b = bh / NH, h = bh % NH;
    const float inv0 = 1.0f / l0, inv1 = 1.0f / l1;
    const int row0 = r0 + wm + g;
#pragma unroll
    for (int nt = 0; nt < 8; ++nt) {
        const int col = h * 64 + nt * 8 + 2 * t;
        *(float2*)&g_o[((size_t)b * SEQ + row0) * CH + col] =
            make_float2(o[nt][0] * inv0, o[nt][1] * inv0);
        *(float2*)&g_o[((size_t)b * SEQ + row0 + 8) * CH + col] =
            make_float2(o[nt][2] * inv1, o[nt][3] * inv1);
    }
}

// =====================================================================
// launch
// =====================================================================
extern "C" void kernel_launch(void* const* d_in, const int* in_sizes, int n_in,
                              void* d_out, int out_size)
{
    (void)in_sizes; (void)n_in; (void)out_size;
    const float* x      = (const float*)d_in[0];
    const float* w_qkv  = (const float*)d_in[1];
    const float* w_proj = (const float*)d_in[2];
    const float* b_proj = (const float*)d_in[3];
    float* out = (float*)d_out;

    cudaFuncSetAttribute((const void*)attn_mma,
                         cudaFuncAttributeMaxDynamicSharedMemorySize, 176128);

    qkv_mma<<<dim3(18, 64), 256>>>(x, w_qkv);
    attn_mma<<<dim3(16, 48), 256, 176128>>>();
    proj_mma<<<dim3(6, 64), 256>>>(w_proj, b_proj, out);
}

// round 6
// speedup vs baseline: 3.0711x; 1.2537x over previous
#include <cuda_runtime.h>
#include <cstdint>

// ---------------- problem constants ----------------
#define BSZ  4
#define SEQ  2048
#define CH   768
#define NH   12
#define HD   64
#define BHN  (BSZ*NH)          // 48

// ---------------- tiled tf32 scratch (uint32 = tf32 bits) ----------------
// GEMM A/B tiles: PT272 chunk = 2176 words (16k x 128col)
__device__ __align__(16) uint32_t g_xt [(size_t)64*48*2176];   // x  tiled [mblk][kt]
__device__ __align__(16) uint32_t g_wqt[(size_t)18*48*2176];   // w_qkv    [nblk][kt]
__device__ __align__(16) uint32_t g_wpt[(size_t) 6*48*2176];   // w_proj   [nblk][kt]
__device__ __align__(16) uint32_t g_ot [(size_t)64*48*2176];   // attn out [mblk][kt]
// Attention tiles per (bh, 128-block)
__device__ __align__(16) uint32_t g_qt [(size_t)BHN*16*8704];  // Q PT272 (k=d64, col=tok)
__device__ __align__(16) uint32_t g_kt [(size_t)BHN*16*8704];  // K PT272
__device__ __align__(16) uint32_t g_vt [(size_t)BHN*16*9216];  // V PT144 (k=kv128, col=d)

// ---------------- helpers ----------------
__device__ __forceinline__ uint32_t f2tf32(float x) {
    uint32_t u; asm("cvt.rna.tf32.f32 %0, %1;" : "=r"(u) : "f"(x)); return u;
}
__device__ __forceinline__ uint32_t fsw(uint32_t x) { return x ^ (x >> 2); }

__device__ __forceinline__ uint32_t s2u(const void* p) {
    uint32_t a;
    asm("{ .reg .u64 t; cvta.to.shared.u64 t, %1; cvt.u32.u64 %0, t; }"
        : "=r"(a) : "l"(p));
    return a;
}
__device__ __forceinline__ void cp16(uint32_t dst, const void* src) {
    asm volatile("cp.async.cg.shared.global [%0], [%1], 16;"
                 :: "r"(dst), "l"(src) : "memory");
}
#define CP_COMMIT() asm volatile("cp.async.commit_group;" ::: "memory")
#define CP_WAIT1()  asm volatile("cp.async.wait_group 1;" ::: "memory")
#define CP_WAIT2()  asm volatile("cp.async.wait_group 2;" ::: "memory")

// D += A(16x8,row) * B(8x8,col)  tf32
__device__ __forceinline__ void mma8(float* c, const uint32_t* a, const uint32_t* b) {
    asm("mma.sync.aligned.m16n8k8.row.col.f32.tf32.tf32.f32 "
        "{%0,%1,%2,%3}, {%4,%5,%6,%7}, {%8,%9}, {%0,%1,%2,%3};"
        : "+f"(c[0]), "+f"(c[1]), "+f"(c[2]), "+f"(c[3])
        : "r"(a[0]), "r"(a[1]), "r"(a[2]), "r"(a[3]), "r"(b[0]), "r"(b[1]));
}
__device__ __forceinline__ float fidx(const float4& v, int s) {
    return (s == 0) ? v.x : (s == 1) ? v.y : (s == 2) ? v.z : v.w;
}

// PT272: element (k, col), k in 0..(8q-1): word offset
__device__ __forceinline__ uint32_t off272(int k, int col) {
    return (uint32_t)((((k >> 3) * 4 + (k & 3)) * 272
                      + 2 * fsw((uint32_t)(col ^ ((k & 3) << 2))) + ((k >> 2) & 1)));
}
// PT144 for V: element (kv, d)
__device__ __forceinline__ uint32_t offv(int kv, int d) {
    return (uint32_t)((((kv >> 3) * 4 + (kv & 3)) * 144
                      + 2 * fsw((uint32_t)(d ^ ((kv & 3) << 2))) + ((kv >> 2) & 1)));
}

// =====================================================================
// Prep: x [8192][768] -> g_xt tiles (tf32)
// =====================================================================
__global__ void prep_x(const float* __restrict__ x)
{
    const int idx = blockIdx.x * 256 + threadIdx.x;   // 8192*192 total
    const int m  = idx / 192;
    const int k4 = (idx - m * 192) * 4;
    const float4 v = *(const float4*)(x + (size_t)m * CH + k4);
    uint32_t* tile = g_xt + ((size_t)(m >> 7) * 48 + (k4 >> 4)) * 2176;
    const int ml = m & 127;
#pragma unroll
    for (int s = 0; s < 4; ++s)
        tile[off272((k4 + s) & 15, ml)] = f2tf32(fidx(v, s));
}

// Prep: w [768][N] -> tiles (tf32). which=0: w_qkv (N=2304), 1: w_proj (N=768)
__global__ void prep_w(const float* __restrict__ w, int which)
{
    const int N = which ? CH : 3 * CH;
    uint32_t* dst = which ? g_wpt : g_wqt;
    const int idx = blockIdx.x * 256 + threadIdx.x;   // 768*N/4
    const int npr = N / 4;
    const int k  = idx / npr;
    const int n4 = (idx - k * npr) * 4;
    const float4 v = *(const float4*)(w + (size_t)k * N + n4);
    uint32_t* tile = dst + ((size_t)(n4 >> 7) * 48 + (k >> 4)) * 2176;
    const int kl = k & 15, nl = n4 & 127;
#pragma unroll
    for (int s = 0; s < 4; ++s)
        tile[off272(kl, nl + s)] = f2tf32(fidx(v, s));
}

// =====================================================================
// GEMM core: 128x128 tile, tiles streamed via cp.async, 4 stages.
// smem: 4 stages x (A 2176 + B 2176) words = 69632 B dynamic.
// =====================================================================
__device__ __forceinline__ void gemm_core(const uint32_t* __restrict__ gA,
                                          const uint32_t* __restrict__ gB,
                                          float acc[2][8][4])
{
    extern __shared__ __align__(16) uint32_t smw[];
    const uint32_t sb = s2u(smw);

    const int tid = threadIdx.x;
    const int lane = tid & 31, wid = tid >> 5;
    const int g = lane >> 2, t = lane & 3;
    const int wm = (wid >> 1) * 32, wn = (wid & 1) * 64;

    uint32_t aFr[2][2], bFr[8];
#pragma unroll
    for (int mt = 0; mt < 2; ++mt)
#pragma unroll
        for (int h = 0; h < 2; ++h)
            aFr[mt][h] = (uint32_t)(t * 272
                        + 2 * fsw((uint32_t)((wm + mt * 16 + g + 8 * h) ^ (t << 2))));
#pragma unroll
    for (int nt = 0; nt < 8; ++nt)
        bFr[nt] = (uint32_t)(2176 + t * 272
                 + 2 * fsw((uint32_t)((wn + nt * 8 + g) ^ (t << 2))));

#pragma unroll
    for (int mt = 0; mt < 2; ++mt)
#pragma unroll
        for (int nt = 0; nt < 8; ++nt)
#pragma unroll
            for (int j = 0; j < 4; ++j) acc[mt][nt][j] = 0.f;

    // async tile copy: stage s holds A(2176) then B(2176); 1088 16B atoms
    auto copy = [&](int kt, int stg) {
        const uint32_t d0 = sb + (uint32_t)stg * 17408u;
        const uint32_t* sA = gA + (size_t)kt * 2176;
        const uint32_t* sB = gB + (size_t)kt * 2176;
#pragma unroll
        for (int rep = 0; rep < 5; ++rep) {
            const int i = tid + rep * 256;
            if (i < 1088) {
                const uint32_t* src = (i < 544) ? (sA + i * 4) : (sB + (i - 544) * 4);
                cp16(d0 + (uint32_t)i * 16u, src);
            }
        }
    };

    copy(0, 0); CP_COMMIT();
    copy(1, 1); CP_COMMIT();
    copy(2, 2); CP_COMMIT();

    for (int kt = 0; kt < 48; kt += 4) {
#pragma unroll
        for (int u = 0; u < 4; ++u) {
            const int kc = kt + u;
            CP_WAIT2();
            __syncthreads();
            if (kc + 3 < 48) copy(kc + 3, (u + 3) & 3);
            CP_COMMIT();
            const uint32_t* st = smw + (u & 3) * 4352;
#pragma unroll
            for (int ks = 0; ks < 2; ++ks) {
                uint2 aw00 = *(const uint2*)&st[ks * 1088 + aFr[0][0]];
                uint2 aw01 = *(const uint2*)&st[ks * 1088 + aFr[0][1]];
                uint2 aw10 = *(const uint2*)&st[ks * 1088 + aFr[1][0]];
                uint2 aw11 = *(const uint2*)&st[ks * 1088 + aFr[1][1]];
                uint32_t a0[4] = {aw00.x, aw01.x, aw00.y, aw01.y};
                uint32_t a1[4] = {aw10.x, aw11.x, aw10.y, aw11.y};
#pragma unroll
                for (int nt = 0; nt < 8; ++nt) {
                    uint2 bw = *(const uint2*)&st[ks * 1088 + bFr[nt]];
                    uint32_t b[2] = {bw.x, bw.y};
                    mma8(acc[0][nt], a0, b);
                    mma8(acc[1][nt], a1, b);
                }
            }
        }
    }
}

// =====================================================================
// GEMM 1: qkv; epilogue scatters tf32 PT tiles for Q/K/V (Q pre-scaled)
// =====================================================================
__global__ __launch_bounds__(256, 2) void qkv_mma()
{
    float acc[2][8][4];
    const uint32_t* gA = g_xt  + (size_t)blockIdx.y * 48 * 2176;
    const uint32_t* gB = g_wqt + (size_t)blockIdx.x * 48 * 2176;
    gemm_core(gA, gB, acc);

    const int tid = threadIdx.x;
    const int lane = tid & 31, wid = tid >> 5;
    const int g = lane >> 2, t = lane & 3;
    const int wm = (wid >> 1) * 32, wn = (wid & 1) * 64;
    const int m0 = blockIdx.y * 128;

    const int t3 = blockIdx.x / 6;               // 0:q 1:k 2:v
    const int nb = (blockIdx.x % 6) * 128;
    const float qs = (t3 == 0) ? 0.125f : 1.0f;

#pragma unroll
    for (int mt = 0; mt < 2; ++mt) {
        const int r = m0 + wm + mt * 16 + g;
        const int b = r >> 11, n = r & (SEQ - 1);
        const int nl = n & 127, nblk = n >> 7;
#pragma unroll
        for (int nt = 0; nt < 8; ++nt) {
            const int cb = nb + wn + nt * 8 + 2 * t;
            const int h = cb >> 6, d = cb & 63;
            const size_t tb = (size_t)(b * NH + h) * 16 + nblk;
            if (t3 < 2) {
                uint32_t* tile = ((t3 == 0) ? g_qt : g_kt) + tb * 8704;
                tile[off272(d,     nl    )] = f2tf32(acc[mt][nt][0] * qs);
                tile[off272(d + 1, nl    )] = f2tf32(acc[mt][nt][1] * qs);
                tile[off272(d,     nl + 8)] = f2tf32(acc[mt][nt][2] * qs);
                tile[off272(d + 1, nl + 8)] = f2tf32(acc[mt][nt][3] * qs);
            } else {
                uint32_t* tile = g_vt + tb * 9216;
                tile[offv(nl,     d    )] = f2tf32(acc[mt][nt][0]);
                tile[offv(nl,     d + 1)] = f2tf32(acc[mt][nt][1]);
                tile[offv(nl + 8, d    )] = f2tf32(acc[mt][nt][2]);
                tile[offv(nl + 8, d + 1)] = f2tf32(acc[mt][nt][3]);
            }
        }
    }
}

// =====================================================================
// GEMM 2: out = o @ w_proj + bias (fp32 out)
// =====================================================================
__global__ __launch_bounds__(256, 2) void proj_mma(const float* __restrict__ bias,
                                                   float* __restrict__ out)
{
    float acc[2][8][4];
    const uint32_t* gA = g_ot  + (size_t)blockIdx.y * 48 * 2176;
    const uint32_t* gB = g_wpt + (size_t)blockIdx.x * 48 * 2176;
    gemm_core(gA, gB, acc);

    const int tid = threadIdx.x;
    const int lane = tid & 31, wid = tid >> 5;
    const int g = lane >> 2, t = lane & 3;
    const int wm = (wid >> 1) * 32, wn = (wid & 1) * 64;
    const int m0 = blockIdx.y * 128, n0 = blockIdx.x * 128;

#pragma unroll
    for (int mt = 0; mt < 2; ++mt) {
        const int r = m0 + wm + mt * 16 + g;
#pragma unroll
        for (int nt = 0; nt < 8; ++nt) {
            const int col = n0 + wn + nt * 8 + 2 * t;
            const float2 bv = *(const float2*)(bias + col);
            float* p = out + (size_t)r * CH + col;
            *(float2*)p = make_float2(acc[mt][nt][0] + bv.x, acc[mt][nt][1] + bv.y);
            *(float2*)(p + 8 * CH) = make_float2(acc[mt][nt][2] + bv.x,
                                                 acc[mt][nt][3] + bv.y);
        }
    }
}

// =====================================================================
// Flash attention (causal), cp.async pipelined.
// smem words: Q @0 (8704), K0 @8704, K1 @17408, V @26112 (9216),
//             P @35328 (17408). Total 52736 w = 210944 B.
// =====================================================================
#define AQ_O 0
#define AK_O 8704
#define AV_O 26112
#define AP_O 35328

__global__ __launch_bounds__(256, 1) void attn_mma()
{
    extern __shared__ __align__(16) uint32_t sm[];
    const uint32_t sb = s2u(sm);

    const int bh = blockIdx.y;
    const int it = (gridDim.x - 1) - blockIdx.x;   // longest first
    const int r0 = it * 128;

    const int tid  = threadIdx.x;
    const int lane = tid & 31;
    const int wid  = tid >> 5;
    const int g    = lane >> 2;
    const int t    = lane & 3;
    const int wm   = wid * 16;

    // ---- fragment / store word offsets ----
    uint32_t qaF[2], paF[2], vbF[8], kbF[16], pSt[2][2];
#pragma unroll
    for (int h = 0; h < 2; ++h) {
        const uint32_t x = 2 * fsw((uint32_t)((wm + g + 8 * h) ^ (t << 2)));
        qaF[h] = AQ_O + t * 272 + x;
        paF[h] = AP_O + t * 272 + x;
    }
#pragma unroll
    for (int nt = 0; nt < 16; ++nt)
        kbF[nt] = t * 272 + 2 * fsw((uint32_t)((nt * 8 + g) ^ (t << 2)));
#pragma unroll
    for (int nt = 0; nt < 8; ++nt)
        vbF[nt] = AV_O + t * 144 + 2 * fsw((uint32_t)((nt * 8 + g) ^ (t << 2)));
#pragma unroll
    for (int b = 0; b < 2; ++b) {
        const int c3 = (2 * t + b) & 3;
        const int e  = (2 * t + b) >> 2;
#pragma unroll
        for (int rh = 0; rh < 2; ++rh)
            pSt[b][rh] = AP_O + c3 * 272
                       + 2 * fsw((uint32_t)((wm + g + 8 * rh) ^ (c3 << 2))) + e;
    }

    // ---- async copies ----
    const uint32_t* Qg = g_qt + ((size_t)bh * 16 + it) * 8704;
    auto copyQ = [&]() {
#pragma unroll
        for (int rep = 0; rep < 9; ++rep) {
            const int i = tid + rep * 256;
            if (i < 2176) cp16(sb + AQ_O * 4 + (uint32_t)i * 16u, Qg + i * 4);
        }
    };
    auto copyK = [&](int j, int buf) {
        const uint32_t* src = g_kt + ((size_t)bh * 16 + j) * 8704;
        const uint32_t d0 = sb + (AK_O + buf * 8704) * 4;
#pragma unroll
        for (int rep = 0; rep < 9; ++rep) {
            const int i = tid + rep * 256;
            if (i < 2176) cp16(d0 + (uint32_t)i * 16u, src + i * 4);
        }
    };
    auto copyV = [&](int j) {
        const uint32_t* src = g_vt + ((size_t)bh * 16 + j) * 9216;
        const uint32_t d0 = sb + AV_O * 4;
#pragma unroll
        for (int rep = 0; rep < 9; ++rep) {
            const int i = tid + rep * 256;
            if (i < 2304) cp16(d0 + (uint32_t)i * 16u, src + i * 4);
        }
    };

    // prologue: G0 = {Q, K0, V0}; G1 = {K1 or empty}
    copyQ(); copyK(0, 0); copyV(0); CP_COMMIT();
    if (it >= 1) copyK(1, 1);
    CP_COMMIT();

    float o[8][4];
    float m0r = -1e30f, m1r = -1e30f, l0 = 0.f, l1 = 0.f;
#pragma unroll
    for (int nt = 0; nt < 8; ++nt)
        o[nt][0] = o[nt][1] = o[nt][2] = o[nt][3] = 0.f;

    for (int jt = 0; jt <= it; ++jt) {
        const int c0 = jt * 128;
        CP_WAIT1();           // K_jt, V_jt (and Q) landed
        __syncthreads();

        const uint32_t kb = AK_O + (uint32_t)(jt & 1) * 8704;

        // ---- S = Q @ K^T ----
        float s[16][4];
#pragma unroll
        for (int nt = 0; nt < 16; ++nt)
            s[nt][0] = s[nt][1] = s[nt][2] = s[nt][3] = 0.f;

#pragma unroll
        for (int ks = 0; ks < 8; ++ks) {
            uint2 aw0 = *(const uint2*)&sm[ks * 1088 + qaF[0]];
            uint2 aw1 = *(const uint2*)&sm[ks * 1088 + qaF[1]];
            uint32_t a[4] = {aw0.x, aw1.x, aw0.y, aw1.y};
#pragma unroll
            for (int nt = 0; nt < 16; ++nt) {
                uint2 bw = *(const uint2*)&sm[kb + ks * 1088 + kbF[nt]];
                uint32_t b[2] = {bw.x, bw.y};
                mma8(s[nt], a, b);
            }
        }

        // ---- causal mask + online softmax ----
        if (jt == it) {
            const int rg0 = r0 + wm + g, rg1 = rg0 + 8;
#pragma unroll
            for (int nt = 0; nt < 16; ++nt) {
                const int cg = c0 + nt * 8 + 2 * t;
                if (cg     > rg0) s[nt][0] = -1e30f;
                if (cg + 1 > rg0) s[nt][1] = -1e30f;
                if (cg     > rg1) s[nt][2] = -1e30f;
                if (cg + 1 > rg1) s[nt][3] = -1e30f;
            }
        }

        float mx0 = -1e30f, mx1 = -1e30f;
#pragma unroll
        for (int nt = 0; nt < 16; ++nt) {
            mx0 = fmaxf(mx0, fmaxf(s[nt][0], s[nt][1]));
            mx1 = fmaxf(mx1, fmaxf(s[nt][2], s[nt][3]));
        }
        mx0 = fmaxf(mx0, __shfl_xor_sync(0xffffffffu, mx0, 1));
        mx0 = fmaxf(mx0, __shfl_xor_sync(0xffffffffu, mx0, 2));
        mx1 = fmaxf(mx1, __shfl_xor_sync(0xffffffffu, mx1, 1));
        mx1 = fmaxf(mx1, __shfl_xor_sync(0xffffffffu, mx1, 2));

        const float mn0 = fmaxf(m0r, mx0);
        const float mn1 = fmaxf(m1r, mx1);
        const float cr0 = __expf(m0r - mn0);
        const float cr1 = __expf(m1r - mn1);

        float sum0 = 0.f, sum1 = 0.f;
#pragma unroll
        for (int nt = 0; nt < 16; ++nt) {
            s[nt][0] = __expf(s[nt][0] - mn0);
            s[nt][1] = __expf(s[nt][1] - mn0);
            s[nt][2] = __expf(s[nt][2] - mn1);
            s[nt][3] = __expf(s[nt][3] - mn1);
            sum0 += s[nt][0] + s[nt][1];
            sum1 += s[nt][2] + s[nt][3];
        }
        sum0 += __shfl_xor_sync(0xffffffffu, sum0, 1);
        sum0 += __shfl_xor_sync(0xffffffffu, sum0, 2);
        sum1 += __shfl_xor_sync(0xffffffffu, sum1, 1);
        sum1 += __shfl_xor_sync(0xffffffffu, sum1, 2);

        l0 = l0 * cr0 + sum0;  m0r = mn0;
        l1 = l1 * cr1 + sum1;  m1r = mn1;
#pragma unroll
        for (int nt = 0; nt < 8; ++nt) {
            o[nt][0] *= cr0; o[nt][1] *= cr0;
            o[nt][2] *= cr1; o[nt][3] *= cr1;
        }

        // ---- P -> smem PT (own-warp rows only) ----
#pragma unroll
        for (int nt = 0; nt < 16; ++nt) {
            sm[nt * 1088 + pSt[0][0]] = f2tf32(s[nt][0]);
            sm[nt * 1088 + pSt[1][0]] = f2tf32(s[nt][1]);
            sm[nt * 1088 + pSt[0][1]] = f2tf32(s[nt][2]);
            sm[nt * 1088 + pSt[1][1]] = f2tf32(s[nt][3]);
        }
        __syncwarp();

        // ---- O += P @ V ----
#pragma unroll
        for (int ks = 0; ks < 16; ++ks) {
            uint2 aw0 = *(const uint2*)&sm[ks * 1088 + paF[0]];
            uint2 aw1 = *(const uint2*)&sm[ks * 1088 + paF[1]];
            uint32_t a[4] = {aw0.x, aw1.x, aw0.y, aw1.y};
#pragma unroll
            for (int nt = 0; nt < 8; ++nt) {
                uint2 bw = *(const uint2*)&sm[ks * 576 + vbF[nt]];
                uint32_t b[2] = {bw.x, bw.y};
                mma8(o[nt], a, b);
            }
        }
        __syncthreads();      // all warps done with V buf / K buf

        if (jt < it) {
            copyV(jt + 1); CP_COMMIT();
            if (jt + 2 <= it) copyK(jt + 2, jt & 1);
            CP_COMMIT();
        }
    }

    // ---- normalize + write PT-A tiles for proj ----
    const int b = bh / NH, h = bh % NH;
    const float inv0 = 1.0f / l0, inv1 = 1.0f / l1;
    const int mblk = (int)(((size_t)b * SEQ + r0) >> 7);
    const int ml0 = wm + g, ml1 = ml0 + 8;
#pragma unroll
    for (int nt = 0; nt < 8; ++nt) {
        const int c = h * 64 + nt * 8 + 2 * t;
        uint32_t* tile = g_ot + ((size_t)mblk * 48 + (c >> 4)) * 2176;
        const int kl = c & 15;
        tile[off272(kl,     ml0)] = f2tf32(o[nt][0] * inv0);
        tile[off272(kl + 1, ml0)] = f2tf32(o[nt][1] * inv0);
        tile[off272(kl,     ml1)] = f2tf32(o[nt][2] * inv1);
        tile[off272(kl + 1, ml1)] = f2tf32(o[nt][3] * inv1);
    }
}

// =====================================================================
// launch
// =====================================================================
extern "C" void kernel_launch(void* const* d_in, const int* in_sizes, int n_in,
                              void* d_out, int out_size)
{
    (void)in_sizes; (void)n_in; (void)out_size;
    const float* x      = (const float*)d_in[0];
    const float* w_qkv  = (const float*)d_in[1];
    const float* w_proj = (const float*)d_in[2];
    const float* b_proj = (const float*)d_in[3];
    float* out = (float*)d_out;

    cudaFuncSetAttribute((const void*)qkv_mma,
                         cudaFuncAttributeMaxDynamicSharedMemorySize, 69632);
    cudaFuncSetAttribute((const void*)proj_mma,
                         cudaFuncAttributeMaxDynamicSharedMemorySize, 69632);
    cudaFuncSetAttribute((const void*)attn_mma,
                         cudaFuncAttributeMaxDynamicSharedMemorySize, 210944);

    prep_x<<<6144, 256>>>(x);
    prep_w<<<1728, 256>>>(w_qkv, 0);
    prep_w<<<576, 256>>>(w_proj, 1);
    qkv_mma<<<dim3(18, 64), 256, 69632>>>();
    attn_mma<<<dim3(16, 48), 256, 210944>>>();
    proj_mma<<<dim3(6, 64), 256, 69632>>>(b_proj, out);
}